// round 11
// baseline (speedup 1.0000x reference)
#include <cuda_runtime.h>
#include <cuda_bf16.h>
#include <stdint.h>
#include <math.h>

// Problem constants
#define SS     5
#define BB     32
#define TT     25
#define TSTEP  24          // T-1 recurrence steps
#define VV     32000
#define EE     512
#define HH     1024
#define GG     3072        // 3*H
#define NROWS  (SS*TSTEP*BB)   // 3840
#define KSPL   2           // K split for step GEMMs (K=1024 -> chunks of 512)
#define KP     (HH/2)      // 512 packed uint2 per row (hi-pair, lo-pair)
#define KPE    (EE/2)      // 256 packed uint2 per embedding row
#define NCTA   296         // persistent kernel grid (2 CTAs/SM on 148 SMs)

// ---------------- scratch (static device globals; no allocation) ----------------
__device__ float d_gi0  [(size_t)NROWS * GG];        // precomputed layer0 gi
__device__ float d_hs0  [(size_t)NROWS * HH];        // layer0 hidden per step (fp32)
__device__ float d_hs1  [(size_t)NROWS * HH];        // layer1 hidden per step (fp32)
__device__ float d_hc0  [BB*HH];                     // carry state layer0 (fp32)
__device__ float d_hc1  [BB*HH];                     // carry state layer1 (fp32)
__device__ float d_p0   [(size_t)KSPL*GG*BB];        // gh0 K-split partials
__device__ float d_p1i  [(size_t)KSPL*GG*BB];        // gi1 partials
__device__ float d_p1h  [(size_t)KSPL*GG*BB];        // gh1 partials

// packed split-bf16 operands: uint2 per 2 k-elems: {x = hi|hi<<16, y = lo|lo<<16}
__device__ uint2 d_xp  [(size_t)NROWS*KPE];          // embeddings packed (7.9MB)
__device__ uint2 d_WpI0[(size_t)GG*KPE];             // W_ih0 packed (6.3MB)
__device__ uint2 d_Wp0 [(size_t)GG*KP];              // W_hh0 packed (12.6MB)
__device__ uint2 d_Wp1i[(size_t)GG*KP];              // W_ih1 packed
__device__ uint2 d_Wp1h[(size_t)GG*KP];              // W_hh1 packed
__device__ uint2 d_WpO [(size_t)VV*KP];              // W_out packed (131MB)
__device__ uint2 d_hs0p[(size_t)NROWS*KP];           // layer0 hidden packed
__device__ uint2 d_hs1p[(size_t)NROWS*KP];           // layer1 hidden packed (logits A)
__device__ uint2 d_hc0p[(size_t)BB*KP];              // carry packed
__device__ uint2 d_hc1p[(size_t)BB*KP];

// software grid barrier state (separate cache lines)
__device__ unsigned d_bar_count = 0;
__device__ unsigned d_bar_pad[31];
__device__ unsigned d_bar_gen = 0;

// ---------------- helpers -------------------------------------------------------
__device__ __forceinline__ uint2 packpair(float x, float y) {
    __nv_bfloat16 hx = __float2bfloat16_rn(x);
    __nv_bfloat16 hy = __float2bfloat16_rn(y);
    float rx = x - __bfloat162float(hx);
    float ry = y - __bfloat162float(hy);
    __nv_bfloat16 lx = __float2bfloat16_rn(rx);
    __nv_bfloat16 ly = __float2bfloat16_rn(ry);
    unsigned short uhx = __bfloat16_as_ushort(hx);
    unsigned short uhy = __bfloat16_as_ushort(hy);
    unsigned short ulx = __bfloat16_as_ushort(lx);
    unsigned short uly = __bfloat16_as_ushort(ly);
    uint2 o;
    o.x = (unsigned int)uhx | ((unsigned int)uhy << 16);
    o.y = (unsigned int)ulx | ((unsigned int)uly << 16);
    return o;
}

__device__ __forceinline__ void mma16816(float& d0, float& d1, float& d2, float& d3,
                                         unsigned int a0, unsigned int a1,
                                         unsigned int a2, unsigned int a3,
                                         unsigned int b0, unsigned int b1) {
    asm volatile(
        "mma.sync.aligned.m16n8k16.row.col.f32.bf16.bf16.f32 "
        "{%0,%1,%2,%3}, {%4,%5,%6,%7}, {%8,%9}, {%0,%1,%2,%3};\n"
        : "+f"(d0), "+f"(d1), "+f"(d2), "+f"(d3)
        : "r"(a0), "r"(a1), "r"(a2), "r"(a3), "r"(b0), "r"(b1));
}

// split-bf16: d += Ahi*Bhi + Ahi*Blo + Alo*Bhi
__device__ __forceinline__ void mma3(float* d, uint2 a0, uint2 a1, uint2 a2, uint2 a3,
                                     uint2 b0, uint2 b1) {
    mma16816(d[0], d[1], d[2], d[3], a0.x, a1.x, a2.x, a3.x, b0.x, b1.x);
    mma16816(d[0], d[1], d[2], d[3], a0.x, a1.x, a2.x, a3.x, b0.y, b1.y);
    mma16816(d[0], d[1], d[2], d[3], a0.y, a1.y, a2.y, a3.y, b0.x, b1.x);
}

// grid barrier: all-resident persistent grid, atomic arrive + gen spin
__device__ __forceinline__ void grid_barrier() {
    __threadfence();
    __syncthreads();
    if (threadIdx.x == 0) {
        unsigned gen = *((volatile unsigned*)&d_bar_gen);
        unsigned a = atomicAdd(&d_bar_count, 1u);
        if (a == NCTA - 1) {
            d_bar_count = 0;
            __threadfence();
            *((volatile unsigned*)&d_bar_gen) = gen + 1;
        } else {
            while (*((volatile unsigned*)&d_bar_gen) == gen) { __nanosleep(32); }
        }
        __threadfence();
    }
    __syncthreads();
}

// ---------------- weight packing ------------------------------------------------
__global__ void k_packw(const float* __restrict__ src, uint2* __restrict__ dst, int npairs) {
    int i = blockIdx.x * blockDim.x + threadIdx.x;
    if (i >= npairs) return;
    float2 v = reinterpret_cast<const float2*>(src)[i];
    dst[i] = packpair(v.x, v.y);
}

// ---------------- embedding gather + pack ---------------------------------------
__global__ void k_gather_pack(const int* __restrict__ ids, const float* __restrict__ embed) {
    int gid = blockIdx.x * blockDim.x + threadIdx.x;
    const int total = NROWS * KPE;
    if (gid >= total) return;
    int r   = gid / KPE;
    int c   = gid % KPE;
    int s   = r / (TSTEP*BB);
    int rem = r % (TSTEP*BB);
    int t   = rem / BB;
    int b   = rem % BB;
    int tok = ids[(s*BB + b)*TT + t];
    float2 v = reinterpret_cast<const float2*>(embed + (size_t)tok*EE)[c];
    d_xp[(size_t)r*KPE + c] = packpair(v.x, v.y);
}

// ---------------- gi0 GEMM via split-bf16 mma (M=3840,N=3072,K=512) -------------
// CTA 128x128, 8 warps (2x4), warp 64x32.  grid (30 m-tiles, 24 n-tiles).
__global__ __launch_bounds__(256)
void k_mma_gi0(const float* __restrict__ bias)
{
    int wid = threadIdx.x >> 5, lane = threadIdx.x & 31;
    int g = lane >> 2, tg = lane & 3;
    int wm = wid >> 2, wn = wid & 3;
    int m0 = blockIdx.x * 128 + wm * 64;
    int n0 = blockIdx.y * 128 + wn * 32;

    float acc[4][4][4];
#pragma unroll
    for (int mi = 0; mi < 4; mi++)
#pragma unroll
        for (int q = 0; q < 4; q++)
#pragma unroll
            for (int i = 0; i < 4; i++) acc[mi][q][i] = 0.0f;

#pragma unroll 2
    for (int kc = 0; kc < KPE; kc += 8) {
        uint2 a[4][4];
#pragma unroll
        for (int mi = 0; mi < 4; mi++) {
            const uint2* Ar0 = d_xp + (size_t)(m0 + mi*16 + g    ) * KPE + kc + tg;
            const uint2* Ar1 = d_xp + (size_t)(m0 + mi*16 + g + 8) * KPE + kc + tg;
            a[mi][0] = Ar0[0];
            a[mi][2] = Ar0[4];
            a[mi][1] = Ar1[0];
            a[mi][3] = Ar1[4];
        }
#pragma unroll
        for (int q = 0; q < 4; q++) {
            const uint2* Br = d_WpI0 + (size_t)(n0 + 8*q + g) * KPE + kc + tg;
            uint2 b0 = Br[0];
            uint2 b1 = Br[4];
#pragma unroll
            for (int mi = 0; mi < 4; mi++)
                mma3(acc[mi][q], a[mi][0], a[mi][1], a[mi][2], a[mi][3], b0, b1);
        }
    }

#pragma unroll
    for (int mi = 0; mi < 4; mi++) {
        int mA = m0 + mi*16 + g;
        int mB = mA + 8;
#pragma unroll
        for (int q = 0; q < 4; q++) {
            int col = n0 + 8*q + 2*tg;
            float b0v = bias[col], b1v = bias[col+1];
            *(float2*)(d_gi0 + (size_t)mA*GG + col) = make_float2(acc[mi][q][0] + b0v, acc[mi][q][1] + b1v);
            *(float2*)(d_gi0 + (size_t)mB*GG + col) = make_float2(acc[mi][q][2] + b0v, acc[mi][q][3] + b1v);
        }
    }
}

// ---------------- step GEMM task (device fn, split-bf16 mma) --------------------
// out[(ks*GG + j)*BB + b] = sum_{k in chunk ks} W[j,k] * x[b,k]
// CTA tile 64j x 32b, 4 warps of 16j. K chunk = 512 elems = 256 pairs.
__device__ __forceinline__ void gemm_task(const uint2* __restrict__ W,
                                          const uint2* __restrict__ xp,
                                          float* __restrict__ out, int jt, int ks)
{
    int wid = threadIdx.x >> 5, lane = threadIdx.x & 31;
    int g = lane >> 2, tg = lane & 3;
    int j0 = jt * 64 + wid * 16;
    int kc0 = ks * (KP / KSPL);        // 256 uint2 per chunk

    float acc[4][4];
#pragma unroll
    for (int q = 0; q < 4; q++)
#pragma unroll
        for (int i = 0; i < 4; i++) acc[q][i] = 0.0f;

    const uint2* Wr0 = W + (size_t)(j0 + g    ) * KP + kc0 + tg;
    const uint2* Wr1 = W + (size_t)(j0 + g + 8) * KP + kc0 + tg;

#pragma unroll 2
    for (int kk = 0; kk < KP/KSPL/8; kk++) {   // 32 x k16 steps
        int kc = kk * 8;
        uint2 a0 = Wr0[kc];
        uint2 a2 = Wr0[kc + 4];
        uint2 a1 = Wr1[kc];
        uint2 a3 = Wr1[kc + 4];
#pragma unroll
        for (int q = 0; q < 4; q++) {
            const uint2* xr = xp + (size_t)(8*q + g) * KP + kc0 + kc + tg;
            uint2 b0 = xr[0];
            uint2 b1 = xr[4];
            mma3(acc[q], a0, a1, a2, a3, b0, b1);
        }
    }

#pragma unroll
    for (int q = 0; q < 4; q++) {
        int b = 8*q + 2*tg;
        *(float2*)(out + ((size_t)ks*GG + j0 + g    )*BB + b) = make_float2(acc[q][0], acc[q][1]);
        *(float2*)(out + ((size_t)ks*GG + j0 + g + 8)*BB + b) = make_float2(acc[q][2], acc[q][3]);
    }
}

// ---------------- persistent recurrence kernel ----------------------------------
__global__ __launch_bounds__(128)
void k_recur(const int* __restrict__ lens,
             const float* __restrict__ bhh0,
             const float* __restrict__ bih1,
             const float* __restrict__ bhh1)
{
    int cta = blockIdx.x;
    int e = cta * 128 + threadIdx.x;     // global element id for pointwise phases

    // zero carry state
    if (e < BB*HH/2) {
        reinterpret_cast<float2*>(d_hc0)[e] = make_float2(0.f, 0.f);
        reinterpret_cast<float2*>(d_hc1)[e] = make_float2(0.f, 0.f);
        d_hc0p[e] = make_uint2(0u, 0u);
        d_hc1p[e] = make_uint2(0u, 0u);
    }
    grid_barrier();

    for (int s = 0; s < SS; s++) {
        for (int t = 0; t < TSTEP; t++) {
            // ---- phase G1: gh0 = W_hh0 @ h0(t-1),  gh1 = W_hh1 @ h1(t-1) ----
            if (cta < 192) {
                int mat = cta / 96;
                int r   = cta % 96;
                int jt  = r >> 1;
                int ks  = r & 1;
                if (mat == 0) {
                    const uint2* xp = (t == 0) ? d_hc0p
                                     : (d_hs0p + (size_t)(s*TSTEP + t - 1) * BB * KP);
                    gemm_task(d_Wp0, xp, d_p0, jt, ks);
                } else {
                    const uint2* xp = (t == 0) ? d_hc1p
                                     : (d_hs1p + (size_t)(s*TSTEP + t - 1) * BB * KP);
                    gemm_task(d_Wp1h, xp, d_p1h, jt, ks);
                }
            }
            grid_barrier();

            // ---- phase P1: gru0 pointwise -> h0(t) (fp32 + packed) ----
            if (e < BB*HH/2) {
                int b  = e >> 9;
                int kc = e & 511;
                int i  = kc * 2;

                float gr0 = bhh0[i],      gr1 = bhh0[i+1];
                float gz0 = bhh0[HH+i],   gz1 = bhh0[HH+i+1];
                float gn0 = bhh0[2*HH+i], gn1 = bhh0[2*HH+i+1];
#pragma unroll
                for (int ks = 0; ks < KSPL; ks++) {
                    const float* p = d_p0 + (size_t)ks*GG*BB;
                    gr0 += p[(size_t)(i         )*BB + b]; gr1 += p[(size_t)(i+1       )*BB + b];
                    gz0 += p[(size_t)(HH + i    )*BB + b]; gz1 += p[(size_t)(HH + i+1  )*BB + b];
                    gn0 += p[(size_t)(2*HH + i  )*BB + b]; gn1 += p[(size_t)(2*HH + i+1)*BB + b];
                }
                const float* gi = d_gi0 + ((size_t)(s*TSTEP + t)*BB + b) * GG;
                float2 irv = *(const float2*)(gi + i);
                float2 izv = *(const float2*)(gi + HH + i);
                float2 inv = *(const float2*)(gi + 2*HH + i);

                const float* hp = (t == 0) ? d_hc0 : (d_hs0 + (size_t)(s*TSTEP + t - 1)*BB*HH);
                float2 hpv = *(const float2*)(hp + (size_t)b*HH + i);

                float r0 = 1.0f / (1.0f + expf(-(irv.x + gr0)));
                float r1 = 1.0f / (1.0f + expf(-(irv.y + gr1)));
                float z0 = 1.0f / (1.0f + expf(-(izv.x + gz0)));
                float z1 = 1.0f / (1.0f + expf(-(izv.y + gz1)));
                float n0 = tanhf(inv.x + r0 * gn0);
                float n1 = tanhf(inv.y + r1 * gn1);
                float h0 = (1.0f - z0)*n0 + z0*hpv.x;
                float h1 = (1.0f - z1)*n1 + z1*hpv.y;

                size_t base = ((size_t)(s*TSTEP + t)*BB + b);
                *(float2*)(d_hs0 + base*HH + i) = make_float2(h0, h1);
                d_hs0p[base*KP + kc] = packpair(h0, h1);
            }
            grid_barrier();

            // ---- phase G2: gi1 = W_ih1 @ h0(t) ----
            if (cta < 96) {
                int jt = cta >> 1;
                int ks = cta & 1;
                const uint2* xp = d_hs0p + (size_t)(s*TSTEP + t) * BB * KP;
                gemm_task(d_Wp1i, xp, d_p1i, jt, ks);
            }
            grid_barrier();

            // ---- phase P2: gru1 pointwise -> h1(t) ----
            if (e < BB*HH/2) {
                int b  = e >> 9;
                int kc = e & 511;
                int i  = kc * 2;

                float ir0 = bih1[i],      ir1 = bih1[i+1];
                float iz0 = bih1[HH+i],   iz1 = bih1[HH+i+1];
                float in0 = bih1[2*HH+i], in1 = bih1[2*HH+i+1];
                float gr0 = bhh1[i],      gr1 = bhh1[i+1];
                float gz0 = bhh1[HH+i],   gz1 = bhh1[HH+i+1];
                float gn0 = bhh1[2*HH+i], gn1 = bhh1[2*HH+i+1];
#pragma unroll
                for (int ks = 0; ks < KSPL; ks++) {
                    const float* pi = d_p1i + (size_t)ks*GG*BB;
                    const float* ph = d_p1h + (size_t)ks*GG*BB;
                    ir0 += pi[(size_t)(i         )*BB + b]; ir1 += pi[(size_t)(i+1       )*BB + b];
                    iz0 += pi[(size_t)(HH + i    )*BB + b]; iz1 += pi[(size_t)(HH + i+1  )*BB + b];
                    in0 += pi[(size_t)(2*HH + i  )*BB + b]; in1 += pi[(size_t)(2*HH + i+1)*BB + b];
                    gr0 += ph[(size_t)(i         )*BB + b]; gr1 += ph[(size_t)(i+1       )*BB + b];
                    gz0 += ph[(size_t)(HH + i    )*BB + b]; gz1 += ph[(size_t)(HH + i+1  )*BB + b];
                    gn0 += ph[(size_t)(2*HH + i  )*BB + b]; gn1 += ph[(size_t)(2*HH + i+1)*BB + b];
                }
                const float* hp = (t == 0) ? d_hc1 : (d_hs1 + (size_t)(s*TSTEP + t - 1)*BB*HH);
                float2 hpv = *(const float2*)(hp + (size_t)b*HH + i);

                float r0 = 1.0f / (1.0f + expf(-(ir0 + gr0)));
                float r1 = 1.0f / (1.0f + expf(-(ir1 + gr1)));
                float z0 = 1.0f / (1.0f + expf(-(iz0 + gz0)));
                float z1 = 1.0f / (1.0f + expf(-(iz1 + gz1)));
                float n0 = tanhf(in0 + r0 * gn0);
                float n1 = tanhf(in1 + r1 * gn1);
                float h0 = (1.0f - z0)*n0 + z0*hpv.x;
                float h1 = (1.0f - z1)*n1 + z1*hpv.y;

                size_t base = ((size_t)(s*TSTEP + t)*BB + b);
                *(float2*)(d_hs1 + base*HH + i) = make_float2(h0, h1);
                d_hs1p[base*KP + kc] = packpair(h0, h1);
            }
            grid_barrier();
        }

        // ---- sentence carry: h <- hs[clip(len-2,0,23)] ----
        if (e < BB*HH/2) {
            int b  = e >> 9;
            int kc = e & 511;
            int i  = kc * 2;
            int idx = lens[s*BB + b] - 2;
            if (idx < 0) idx = 0;
            if (idx > TSTEP - 1) idx = TSTEP - 1;
            size_t base = ((size_t)(s*TSTEP + idx)*BB + b);
            *(float2*)(d_hc0 + (size_t)b*HH + i) = *(const float2*)(d_hs0 + base*HH + i);
            *(float2*)(d_hc1 + (size_t)b*HH + i) = *(const float2*)(d_hs1 + base*HH + i);
            d_hc0p[(size_t)b*KP + kc] = d_hs0p[base*KP + kc];
            d_hc1p[(size_t)b*KP + kc] = d_hs1p[base*KP + kc];
        }
        grid_barrier();
    }
}

// ---------------- logits GEMM via split-bf16 mma --------------------------------
// C[m=3840, n=32000] = hs1 @ W_out^T ; CTA 128x128, 8 warps (2x4), warp 64x32.
__global__ __launch_bounds__(256)
void k_mma_logits(float* __restrict__ out)
{
    int wid = threadIdx.x >> 5, lane = threadIdx.x & 31;
    int g = lane >> 2, tg = lane & 3;
    int wm = wid >> 2, wn = wid & 3;
    int m0 = blockIdx.x * 128 + wm * 64;
    int n0 = blockIdx.y * 128 + wn * 32;

    float acc[4][4][4];
#pragma unroll
    for (int mi = 0; mi < 4; mi++)
#pragma unroll
        for (int q = 0; q < 4; q++)
#pragma unroll
            for (int i = 0; i < 4; i++) acc[mi][q][i] = 0.0f;

#pragma unroll 2
    for (int kc = 0; kc < KP; kc += 8) {       // k16 steps over K=1024
        uint2 a[4][4];
#pragma unroll
        for (int mi = 0; mi < 4; mi++) {
            const uint2* Ar0 = d_hs1p + (size_t)(m0 + mi*16 + g    ) * KP + kc + tg;
            const uint2* Ar1 = d_hs1p + (size_t)(m0 + mi*16 + g + 8) * KP + kc + tg;
            a[mi][0] = Ar0[0];
            a[mi][2] = Ar0[4];
            a[mi][1] = Ar1[0];
            a[mi][3] = Ar1[4];
        }
#pragma unroll
        for (int q = 0; q < 4; q++) {
            const uint2* Br = d_WpO + (size_t)(n0 + 8*q + g) * KP + kc + tg;
            uint2 b0 = Br[0];
            uint2 b1 = Br[4];
#pragma unroll
            for (int mi = 0; mi < 4; mi++)
                mma3(acc[mi][q], a[mi][0], a[mi][1], a[mi][2], a[mi][3], b0, b1);
        }
    }

    // epilogue with (s,t,b)->(s,b,t) remap
#pragma unroll
    for (int mi = 0; mi < 4; mi++) {
        int mA = m0 + mi*16 + g;
        int mB = mA + 8;
        int sA = mA / (TSTEP*BB); int rA = mA % (TSTEP*BB);
        int sB = mB / (TSTEP*BB); int rB = mB % (TSTEP*BB);
        size_t rowA = ((size_t)(sA*BB + (rA % BB))*TSTEP + (rA / BB)) * VV;
        size_t rowB = ((size_t)(sB*BB + (rB % BB))*TSTEP + (rB / BB)) * VV;
#pragma unroll
        for (int q = 0; q < 4; q++) {
            int col = n0 + 8*q + 2*tg;
            *(float2*)(out + rowA + col) = make_float2(acc[mi][q][0], acc[mi][q][1]);
            *(float2*)(out + rowB + col) = make_float2(acc[mi][q][2], acc[mi][q][3]);
        }
    }
}

// ---------------- launcher ------------------------------------------------------
extern "C" void kernel_launch(void* const* d_in, const int* in_sizes, int n_in,
                              void* d_out, int out_size)
{
    (void)in_sizes; (void)n_in; (void)out_size;
    const int*   ids    = (const int*)  d_in[0];
    const int*   lens   = (const int*)  d_in[1];
    const float* embed  = (const float*)d_in[2];
    const float* W_ih0  = (const float*)d_in[3];
    const float* W_hh0  = (const float*)d_in[4];
    const float* b_ih0  = (const float*)d_in[5];
    const float* b_hh0  = (const float*)d_in[6];
    const float* W_ih1  = (const float*)d_in[7];
    const float* W_hh1  = (const float*)d_in[8];
    const float* b_ih1  = (const float*)d_in[9];
    const float* b_hh1  = (const float*)d_in[10];
    const float* W_out  = (const float*)d_in[11];
    float*       out    = (float*)d_out;

    uint2* wpi0; cudaGetSymbolAddress((void**)&wpi0, d_WpI0);
    uint2* wp0;  cudaGetSymbolAddress((void**)&wp0,  d_Wp0);
    uint2* wp1i; cudaGetSymbolAddress((void**)&wp1i, d_Wp1i);
    uint2* wp1h; cudaGetSymbolAddress((void**)&wp1h, d_Wp1h);
    uint2* wpo;  cudaGetSymbolAddress((void**)&wpo,  d_WpO);

    // gather + pack embeddings
    k_gather_pack<<<(NROWS*KPE + 255)/256, 256>>>(ids, embed);

    // pack weights into split-bf16 hi/lo pairs
    k_packw<<<(GG*KPE + 255)/256, 256>>>(W_ih0, wpi0, GG*KPE);
    k_packw<<<(GG*KP  + 255)/256, 256>>>(W_hh0, wp0,  GG*KP);
    k_packw<<<(GG*KP  + 255)/256, 256>>>(W_ih1, wp1i, GG*KP);
    k_packw<<<(GG*KP  + 255)/256, 256>>>(W_hh1, wp1h, GG*KP);
    k_packw<<<(VV*KP  + 255)/256, 256>>>(W_out, wpo,  VV*KP);

    // precompute layer-0 input gates: gi0 = x @ W_ih0^T + b_ih0 (tensor cores)
    k_mma_gi0<<<dim3(NROWS/128, GG/128), 256>>>(b_ih0);

    // whole recurrence in ONE persistent kernel (software grid barriers)
    k_recur<<<NCTA, 128>>>(lens, b_hh0, b_ih1, b_hh1);

    // logits = hs1 @ W_out^T (tensor cores), remapped to (s, b, t, v)
    k_mma_logits<<<dim3(NROWS/128, VV/128), 256>>>(out);
}

// round 12
// speedup vs baseline: 1.0499x; 1.0499x over previous
#include <cuda_runtime.h>
#include <cuda_bf16.h>
#include <stdint.h>
#include <math.h>

// Problem constants
#define SS     5
#define BB     32
#define TT     25
#define TSTEP  24          // T-1 recurrence steps
#define VV     32000
#define EE     512
#define HH     1024
#define GG     3072        // 3*H
#define NROWS  (SS*TSTEP*BB)   // 3840
#define KP     (HH/2)      // 512 packed uint2 per row (hi-pair, lo-pair)
#define KPE    (EE/2)      // 256 packed uint2 per embedding row
#define NCTA   128         // persistent recurrence grid (1 CTA per 8 h-outputs)
#define JT     8           // h outputs per CTA

// ---------------- scratch (static device globals; no allocation) ----------------
__device__ float d_gi  [(size_t)NROWS * GG];         // gi buffer (layer0, then layer1)
__device__ float d_hs0 [(size_t)NROWS * HH];         // layer0 hidden (fp32)
__device__ float d_hs1 [(size_t)NROWS * HH];         // layer1 hidden (fp32)

// packed split-bf16: uint2 per 2 k-elems {x = hi|hi<<16, y = lo|lo<<16}
__device__ uint2 d_xp  [(size_t)NROWS*KPE];          // embeddings packed
__device__ uint2 d_WpI0[(size_t)GG*KPE];             // W_ih0 packed
__device__ uint2 d_Wp0 [(size_t)GG*KP];              // W_hh0 packed
__device__ uint2 d_Wp1i[(size_t)GG*KP];              // W_ih1 packed
__device__ uint2 d_Wp1h[(size_t)GG*KP];              // W_hh1 packed
__device__ uint2 d_WpO [(size_t)VV*KP];              // W_out packed (131MB)
__device__ uint2 d_hs0p[(size_t)NROWS*KP];           // layer0 hidden packed
__device__ uint2 d_hs1p[(size_t)NROWS*KP];           // layer1 hidden packed
__device__ uint2 d_zrow[KP];                         // zero packed row
__device__ float d_zf  [HH];                         // zero fp32 row

// grid barrier state (separate lines)
__device__ unsigned d_cnt = 0;
__device__ unsigned d_padA[31];
__device__ unsigned d_gen = 0;

// ---------------- helpers -------------------------------------------------------
__device__ __forceinline__ uint2 packpair(float x, float y) {
    __nv_bfloat16 hx = __float2bfloat16_rn(x);
    __nv_bfloat16 hy = __float2bfloat16_rn(y);
    float rx = x - __bfloat162float(hx);
    float ry = y - __bfloat162float(hy);
    __nv_bfloat16 lx = __float2bfloat16_rn(rx);
    __nv_bfloat16 ly = __float2bfloat16_rn(ry);
    uint2 o;
    o.x = (unsigned int)__bfloat16_as_ushort(hx) | ((unsigned int)__bfloat16_as_ushort(hy) << 16);
    o.y = (unsigned int)__bfloat16_as_ushort(lx) | ((unsigned int)__bfloat16_as_ushort(ly) << 16);
    return o;
}

__device__ __forceinline__ void mma16816(float& d0, float& d1, float& d2, float& d3,
                                         unsigned int a0, unsigned int a1,
                                         unsigned int a2, unsigned int a3,
                                         unsigned int b0, unsigned int b1) {
    asm volatile(
        "mma.sync.aligned.m16n8k16.row.col.f32.bf16.bf16.f32 "
        "{%0,%1,%2,%3}, {%4,%5,%6,%7}, {%8,%9}, {%0,%1,%2,%3};\n"
        : "+f"(d0), "+f"(d1), "+f"(d2), "+f"(d3)
        : "r"(a0), "r"(a1), "r"(a2), "r"(a3), "r"(b0), "r"(b1));
}

// split-bf16: d += Ahi*Bhi + Ahi*Blo + Alo*Bhi
__device__ __forceinline__ void mma3(float* d, uint2 a0, uint2 a1, uint2 a2, uint2 a3,
                                     uint2 b0, uint2 b1) {
    mma16816(d[0], d[1], d[2], d[3], a0.x, a1.x, a2.x, a3.x, b0.x, b1.x);
    mma16816(d[0], d[1], d[2], d[3], a0.x, a1.x, a2.x, a3.x, b0.y, b1.y);
    mma16816(d[0], d[1], d[2], d[3], a0.y, a1.y, a2.y, a3.y, b0.x, b1.x);
}

// CG-style grid barrier: release-atomic arrive, acquire-poll on generation.
__device__ __forceinline__ void gbar() {
    __syncthreads();
    if (threadIdx.x == 0) {
        unsigned g;
        asm volatile("ld.relaxed.gpu.u32 %0, [%1];" : "=r"(g) : "l"(&d_gen));
        unsigned prev;
        asm volatile("atom.release.gpu.add.u32 %0, [%1], %2;"
                     : "=r"(prev) : "l"(&d_cnt), "r"(1u) : "memory");
        if (prev == NCTA - 1) {
            asm volatile("st.relaxed.gpu.u32 [%0], %1;" :: "l"(&d_cnt), "r"(0u) : "memory");
            asm volatile("st.release.gpu.u32 [%0], %1;" :: "l"(&d_gen), "r"(g + 1u) : "memory");
        } else {
            unsigned cur;
            do {
                asm volatile("ld.acquire.gpu.u32 %0, [%1];" : "=r"(cur) : "l"(&d_gen) : "memory");
            } while (cur == g);
        }
    }
    __syncthreads();
}

// ---------------- init / packing -----------------------------------------------
__global__ void k_zero_init() {
    int i = threadIdx.x;
    if (i < KP) d_zrow[i] = make_uint2(0u, 0u);
    d_zf[i] = 0.0f; d_zf[i + 512] = 0.0f;
}

__global__ void k_packw(const float* __restrict__ src, uint2* __restrict__ dst, int npairs) {
    int i = blockIdx.x * blockDim.x + threadIdx.x;
    if (i >= npairs) return;
    float2 v = reinterpret_cast<const float2*>(src)[i];
    dst[i] = packpair(v.x, v.y);
}

__global__ void k_gather_pack(const int* __restrict__ ids, const float* __restrict__ embed) {
    int gid = blockIdx.x * blockDim.x + threadIdx.x;
    const int total = NROWS * KPE;
    if (gid >= total) return;
    int r   = gid / KPE;
    int c   = gid % KPE;
    int s   = r / (TSTEP*BB);
    int rem = r % (TSTEP*BB);
    int t   = rem / BB;
    int b   = rem % BB;
    int tok = ids[(s*BB + b)*TT + t];
    float2 v = reinterpret_cast<const float2*>(embed + (size_t)tok*EE)[c];
    d_xp[(size_t)r*KPE + c] = packpair(v.x, v.y);
}

// ---------------- big GEMM: C[M=3840, N=3072] = A @ Bw^T + bias -----------------
// CTA 128x128, 8 warps (2x4), warp 64x32.  Kp = packed-pair count (256 or 512).
__global__ __launch_bounds__(256)
void k_mma_big(const uint2* __restrict__ A, const uint2* __restrict__ Bw,
               const float* __restrict__ bias, float* __restrict__ C, int Kp)
{
    int wid = threadIdx.x >> 5, lane = threadIdx.x & 31;
    int g = lane >> 2, tg = lane & 3;
    int wm = wid >> 2, wn = wid & 3;
    int m0 = blockIdx.x * 128 + wm * 64;
    int n0 = blockIdx.y * 128 + wn * 32;

    float acc[4][4][4];
#pragma unroll
    for (int mi = 0; mi < 4; mi++)
#pragma unroll
        for (int q = 0; q < 4; q++)
#pragma unroll
            for (int i = 0; i < 4; i++) acc[mi][q][i] = 0.0f;

#pragma unroll 2
    for (int kc = 0; kc < Kp; kc += 8) {
        uint2 a[4][4];
#pragma unroll
        for (int mi = 0; mi < 4; mi++) {
            const uint2* Ar0 = A + (size_t)(m0 + mi*16 + g    ) * Kp + kc + tg;
            const uint2* Ar1 = A + (size_t)(m0 + mi*16 + g + 8) * Kp + kc + tg;
            a[mi][0] = Ar0[0];
            a[mi][2] = Ar0[4];
            a[mi][1] = Ar1[0];
            a[mi][3] = Ar1[4];
        }
#pragma unroll
        for (int q = 0; q < 4; q++) {
            const uint2* Br = Bw + (size_t)(n0 + 8*q + g) * Kp + kc + tg;
            uint2 b0 = Br[0];
            uint2 b1 = Br[4];
#pragma unroll
            for (int mi = 0; mi < 4; mi++)
                mma3(acc[mi][q], a[mi][0], a[mi][1], a[mi][2], a[mi][3], b0, b1);
        }
    }

#pragma unroll
    for (int mi = 0; mi < 4; mi++) {
        int mA = m0 + mi*16 + g;
        int mB = mA + 8;
#pragma unroll
        for (int q = 0; q < 4; q++) {
            int col = n0 + 8*q + 2*tg;
            float b0v = bias[col], b1v = bias[col+1];
            *(float2*)(C + (size_t)mA*GG + col) = make_float2(acc[mi][q][0] + b0v, acc[mi][q][1] + b1v);
            *(float2*)(C + (size_t)mB*GG + col) = make_float2(acc[mi][q][2] + b0v, acc[mi][q][3] + b1v);
        }
    }
}

// ---------------- persistent single-layer recurrence ----------------------------
// One fused phase per step: gate GEMM (warps split K) + smem reduce + GRU pointwise
// + h write. ONE grid barrier per step. Sentence carry folded into x-row pointers.
__global__ __launch_bounds__(256, 1)
void k_recur(const uint2* __restrict__ W,      // [GG][KP] packed (W_hh)
             const float* __restrict__ gi,     // [NROWS][GG] input gates (+b_ih)
             const float* __restrict__ bias,   // [GG] b_hh
             float* __restrict__ hs,           // [NROWS][HH]
             uint2* __restrict__ hsp,          // [NROWS][KP]
             const int* __restrict__ lens)
{
    __shared__ float Sp[8][24][33];            // per-warp gate partials
    __shared__ float hbuf[32*9];               // h outputs (padded)
    __shared__ const uint2* xptr[BB];          // per-batch packed hprev row
    __shared__ const float* hpv [BB];          // per-batch fp32 hprev row

    int tid  = threadIdx.x;
    int w    = tid >> 5, lane = tid & 31;
    int g    = lane >> 2, tg = lane & 3;
    int j0   = blockIdx.x * JT;
    int kb   = w * 64;                         // per-warp K chunk (uint2)

    // per-warp gate-row pointers (constant over steps)
    const uint2* Wr = W + (size_t)(j0 + g       ) * KP;
    const uint2* Wz = W + (size_t)(HH + j0 + g  ) * KP;
    const uint2* Wn = W + (size_t)(2*HH + j0 + g) * KP;

    // pointwise mapping: thread -> (j = tid>>5, b = lane)
    int pj = tid >> 5, pb = lane;
    float bR = bias[j0 + pj];
    float bZ = bias[HH + j0 + pj];
    float bN = bias[2*HH + j0 + pj];

    for (int s = 0; s < SS; s++) {
        for (int t = 0; t < TSTEP; t++) {
            int step = s*TSTEP + t;

            // per-batch hprev row pointers (handles sentence carry + zero init)
            if (tid < BB) {
                int b = tid;
                const uint2* xp; const float* hp;
                if (t == 0) {
                    if (s == 0) { xp = d_zrow; hp = d_zf; }
                    else {
                        int idx = lens[(s-1)*BB + b] - 2;
                        idx = idx < 0 ? 0 : (idx > TSTEP-1 ? TSTEP-1 : idx);
                        size_t r = (size_t)((s-1)*TSTEP + idx)*BB + b;
                        xp = hsp + r*KP; hp = hs + r*HH;
                    }
                } else {
                    size_t r = (size_t)(step-1)*BB + b;
                    xp = hsp + r*KP; hp = hs + r*HH;
                }
                xptr[b] = xp; hpv[b] = hp;
            }
            __syncthreads();

            // ---- fused gate GEMM: m=24 gate rows (+8 pad) x n=32 x k=128/warp ----
            const uint2* x0 = xptr[g];
            const uint2* x1 = xptr[8+g];
            const uint2* x2 = xptr[16+g];
            const uint2* x3 = xptr[24+g];

            float acc0[4][4], acc1[4][4];
#pragma unroll
            for (int q = 0; q < 4; q++)
#pragma unroll
                for (int i = 0; i < 4; i++) { acc0[q][i] = 0.0f; acc1[q][i] = 0.0f; }

#pragma unroll
            for (int kk = 0; kk < 8; kk++) {
                int kc = kb + kk*8;
                uint2 ar0 = Wr[kc+tg], ar4 = Wr[kc+tg+4];
                uint2 az0 = Wz[kc+tg], az4 = Wz[kc+tg+4];
                uint2 an0 = Wn[kc+tg], an4 = Wn[kc+tg+4];
                uint2 b0, b1;
                b0 = x0[kc+tg]; b1 = x0[kc+tg+4];
                mma3(acc0[0], ar0, az0, ar4, az4, b0, b1);
                mma3(acc1[0], an0, ar0, an4, ar4, b0, b1);
                b0 = x1[kc+tg]; b1 = x1[kc+tg+4];
                mma3(acc0[1], ar0, az0, ar4, az4, b0, b1);
                mma3(acc1[1], an0, ar0, an4, ar4, b0, b1);
                b0 = x2[kc+tg]; b1 = x2[kc+tg+4];
                mma3(acc0[2], ar0, az0, ar4, az4, b0, b1);
                mma3(acc1[2], an0, ar0, an4, ar4, b0, b1);
                b0 = x3[kc+tg]; b1 = x3[kc+tg+4];
                mma3(acc0[3], ar0, az0, ar4, az4, b0, b1);
                mma3(acc1[3], an0, ar0, an4, ar4, b0, b1);
            }

            // store per-warp partials (tile0: d01=r rows, d23=z rows; tile1: d01=n rows)
#pragma unroll
            for (int q = 0; q < 4; q++) {
                int col = q*8 + 2*tg;
                Sp[w][g     ][col]   = acc0[q][0];
                Sp[w][g     ][col+1] = acc0[q][1];
                Sp[w][8 + g ][col]   = acc0[q][2];
                Sp[w][8 + g ][col+1] = acc0[q][3];
                Sp[w][16 + g][col]   = acc1[q][0];
                Sp[w][16 + g][col+1] = acc1[q][1];
            }
            __syncthreads();

            // ---- reduce 8 warps + GRU pointwise (one thread per (j,b)) ----
            {
                float sr = 0.f, sz = 0.f, sn = 0.f;
#pragma unroll
                for (int ww = 0; ww < 8; ww++) {
                    sr += Sp[ww][pj     ][pb];
                    sz += Sp[ww][8 + pj ][pb];
                    sn += Sp[ww][16 + pj][pb];
                }
                const float* gir = gi + ((size_t)step*BB + pb) * GG;
                float ir  = gir[j0 + pj];
                float iz  = gir[HH + j0 + pj];
                float inn = gir[2*HH + j0 + pj];
                float hprev = hpv[pb][j0 + pj];

                float rr = 1.0f / (1.0f + expf(-(ir + sr + bR)));
                float zz = 1.0f / (1.0f + expf(-(iz + sz + bZ)));
                float nn = tanhf(inn + rr * (sn + bN));
                hbuf[pb*9 + pj] = (1.0f - zz)*nn + zz*hprev;
            }
            __syncthreads();

            // ---- write h (fp32 coalesced 32B segments + packed) ----
            {
                int b = tid >> 3, j = tid & 7;
                size_t row = (size_t)step*BB + b;
                hs[row*HH + j0 + j] = hbuf[b*9 + j];
            }
            if (tid < 128) {
                int b = tid >> 2, jp = tid & 3;
                size_t row = (size_t)step*BB + b;
                hsp[row*KP + (j0 >> 1) + jp] = packpair(hbuf[b*9 + 2*jp], hbuf[b*9 + 2*jp + 1]);
            }

            gbar();   // ONE global sync per step
        }
    }
}

// ---------------- logits GEMM via split-bf16 mma --------------------------------
__global__ __launch_bounds__(256)
void k_mma_logits(float* __restrict__ out)
{
    int wid = threadIdx.x >> 5, lane = threadIdx.x & 31;
    int g = lane >> 2, tg = lane & 3;
    int wm = wid >> 2, wn = wid & 3;
    int m0 = blockIdx.x * 128 + wm * 64;
    int n0 = blockIdx.y * 128 + wn * 32;

    float acc[4][4][4];
#pragma unroll
    for (int mi = 0; mi < 4; mi++)
#pragma unroll
        for (int q = 0; q < 4; q++)
#pragma unroll
            for (int i = 0; i < 4; i++) acc[mi][q][i] = 0.0f;

#pragma unroll 2
    for (int kc = 0; kc < KP; kc += 8) {
        uint2 a[4][4];
#pragma unroll
        for (int mi = 0; mi < 4; mi++) {
            const uint2* Ar0 = d_hs1p + (size_t)(m0 + mi*16 + g    ) * KP + kc + tg;
            const uint2* Ar1 = d_hs1p + (size_t)(m0 + mi*16 + g + 8) * KP + kc + tg;
            a[mi][0] = Ar0[0];
            a[mi][2] = Ar0[4];
            a[mi][1] = Ar1[0];
            a[mi][3] = Ar1[4];
        }
#pragma unroll
        for (int q = 0; q < 4; q++) {
            const uint2* Br = d_WpO + (size_t)(n0 + 8*q + g) * KP + kc + tg;
            uint2 b0 = Br[0];
            uint2 b1 = Br[4];
#pragma unroll
            for (int mi = 0; mi < 4; mi++)
                mma3(acc[mi][q], a[mi][0], a[mi][1], a[mi][2], a[mi][3], b0, b1);
        }
    }

    // epilogue with (s,t,b)->(s,b,t) remap
#pragma unroll
    for (int mi = 0; mi < 4; mi++) {
        int mA = m0 + mi*16 + g;
        int mB = mA + 8;
        int sA = mA / (TSTEP*BB); int rA = mA % (TSTEP*BB);
        int sB = mB / (TSTEP*BB); int rB = mB % (TSTEP*BB);
        size_t rowA = ((size_t)(sA*BB + (rA % BB))*TSTEP + (rA / BB)) * VV;
        size_t rowB = ((size_t)(sB*BB + (rB % BB))*TSTEP + (rB / BB)) * VV;
#pragma unroll
        for (int q = 0; q < 4; q++) {
            int col = n0 + 8*q + 2*tg;
            *(float2*)(out + rowA + col) = make_float2(acc[mi][q][0], acc[mi][q][1]);
            *(float2*)(out + rowB + col) = make_float2(acc[mi][q][2], acc[mi][q][3]);
        }
    }
}

// ---------------- launcher ------------------------------------------------------
extern "C" void kernel_launch(void* const* d_in, const int* in_sizes, int n_in,
                              void* d_out, int out_size)
{
    (void)in_sizes; (void)n_in; (void)out_size;
    const int*   ids    = (const int*)  d_in[0];
    const int*   lens   = (const int*)  d_in[1];
    const float* embed  = (const float*)d_in[2];
    const float* W_ih0  = (const float*)d_in[3];
    const float* W_hh0  = (const float*)d_in[4];
    const float* b_ih0  = (const float*)d_in[5];
    const float* b_hh0  = (const float*)d_in[6];
    const float* W_ih1  = (const float*)d_in[7];
    const float* W_hh1  = (const float*)d_in[8];
    const float* b_ih1  = (const float*)d_in[9];
    const float* b_hh1  = (const float*)d_in[10];
    const float* W_out  = (const float*)d_in[11];
    float*       out    = (float*)d_out;

    uint2* wpi0; cudaGetSymbolAddress((void**)&wpi0, d_WpI0);
    uint2* wp0;  cudaGetSymbolAddress((void**)&wp0,  d_Wp0);
    uint2* wp1i; cudaGetSymbolAddress((void**)&wp1i, d_Wp1i);
    uint2* wp1h; cudaGetSymbolAddress((void**)&wp1h, d_Wp1h);
    uint2* wpo;  cudaGetSymbolAddress((void**)&wpo,  d_WpO);
    uint2* xp;   cudaGetSymbolAddress((void**)&xp,   d_xp);
    uint2* h0p;  cudaGetSymbolAddress((void**)&h0p,  d_hs0p);
    uint2* h1p;  cudaGetSymbolAddress((void**)&h1p,  d_hs1p);
    float* gi;   cudaGetSymbolAddress((void**)&gi,   d_gi);
    float* hs0;  cudaGetSymbolAddress((void**)&hs0,  d_hs0);
    float* hs1;  cudaGetSymbolAddress((void**)&hs1,  d_hs1);

    // zero rows + gather/pack inputs
    k_zero_init<<<1, 512>>>();
    k_gather_pack<<<(NROWS*KPE + 255)/256, 256>>>(ids, embed);
    k_packw<<<(GG*KPE + 255)/256, 256>>>(W_ih0, wpi0, GG*KPE);
    k_packw<<<(GG*KP  + 255)/256, 256>>>(W_hh0, wp0,  GG*KP);
    k_packw<<<(GG*KP  + 255)/256, 256>>>(W_ih1, wp1i, GG*KP);
    k_packw<<<(GG*KP  + 255)/256, 256>>>(W_hh1, wp1h, GG*KP);
    k_packw<<<(VV*KP  + 255)/256, 256>>>(W_out, wpo,  VV*KP);

    // gi(layer0) = x @ W_ih0^T + b_ih0
    k_mma_big<<<dim3(NROWS/128, GG/128), 256>>>(xp, wpi0, b_ih0, gi, KPE);

    // layer-0 recurrence (persistent, 1 barrier/step)
    k_recur<<<NCTA, 256>>>(wp0, gi, b_hh0, hs0, h0p, lens);

    // gi(layer1) = h0_all @ W_ih1^T + b_ih1  (off critical path, one big GEMM)
    k_mma_big<<<dim3(NROWS/128, GG/128), 256>>>(h0p, wp1i, b_ih1, gi, KP);

    // layer-1 recurrence
    k_recur<<<NCTA, 256>>>(wp1h, gi, b_hh1, hs1, h1p, lens);

    // logits = hs1 @ W_out^T, remapped to (s, b, t, v)
    k_mma_logits<<<dim3(NROWS/128, VV/128), 256>>>(out);
}

// round 13
// speedup vs baseline: 1.7694x; 1.6853x over previous
#include <cuda_runtime.h>
#include <cuda_bf16.h>
#include <stdint.h>
#include <math.h>

// Problem constants
#define SS     5
#define BB     32
#define TT     25
#define TSTEP  24          // T-1 recurrence steps
#define VV     32000
#define EE     512
#define HH     1024
#define GG     3072        // 3*H
#define NROWS  (SS*TSTEP*BB)   // 3840
#define KP     (HH/2)      // 512 packed uint2 per row (hi-pair, lo-pair)
#define KPE    (EE/2)      // 256 packed uint2 per embedding row
#define NCTA   128         // persistent recurrence grid (1 CTA per 8 h-outputs)
#define JT     8           // h outputs per CTA
#define WSTRIDE 513        // padded smem row stride (uint2) -> conflict-free g-rows

// ---------------- scratch (static device globals; no allocation) ----------------
__device__ float d_gi  [(size_t)NROWS * GG];         // gi buffer (layer0, then layer1)
__device__ float d_hs0 [(size_t)NROWS * HH];         // layer0 hidden (fp32)
__device__ float d_hs1 [(size_t)NROWS * HH];         // layer1 hidden (fp32)

// packed split-bf16: uint2 per 2 k-elems {x = hi|hi<<16, y = lo|lo<<16}
__device__ uint2 d_xp  [(size_t)NROWS*KPE];          // embeddings packed
__device__ uint2 d_WpI0[(size_t)GG*KPE];             // W_ih0 packed
__device__ uint2 d_Wp0 [(size_t)GG*KP];              // W_hh0 packed
__device__ uint2 d_Wp1i[(size_t)GG*KP];              // W_ih1 packed
__device__ uint2 d_Wp1h[(size_t)GG*KP];              // W_hh1 packed
__device__ uint2 d_WpO [(size_t)VV*KP];              // W_out packed (131MB)
__device__ uint2 d_hs0p[(size_t)NROWS*KP];           // layer0 hidden packed
__device__ uint2 d_hs1p[(size_t)NROWS*KP];           // layer1 hidden packed
__device__ uint2 d_zrow[KP];                         // zero packed row
__device__ float d_zf  [HH];                         // zero fp32 row

// grid barrier state (separate lines)
__device__ unsigned d_cnt = 0;
__device__ unsigned d_padA[31];
__device__ unsigned d_gen = 0;

// ---------------- helpers -------------------------------------------------------
__device__ __forceinline__ uint2 packpair(float x, float y) {
    __nv_bfloat16 hx = __float2bfloat16_rn(x);
    __nv_bfloat16 hy = __float2bfloat16_rn(y);
    float rx = x - __bfloat162float(hx);
    float ry = y - __bfloat162float(hy);
    __nv_bfloat16 lx = __float2bfloat16_rn(rx);
    __nv_bfloat16 ly = __float2bfloat16_rn(ry);
    uint2 o;
    o.x = (unsigned int)__bfloat16_as_ushort(hx) | ((unsigned int)__bfloat16_as_ushort(hy) << 16);
    o.y = (unsigned int)__bfloat16_as_ushort(lx) | ((unsigned int)__bfloat16_as_ushort(ly) << 16);
    return o;
}

__device__ __forceinline__ void mma16816(float& d0, float& d1, float& d2, float& d3,
                                         unsigned int a0, unsigned int a1,
                                         unsigned int a2, unsigned int a3,
                                         unsigned int b0, unsigned int b1) {
    asm volatile(
        "mma.sync.aligned.m16n8k16.row.col.f32.bf16.bf16.f32 "
        "{%0,%1,%2,%3}, {%4,%5,%6,%7}, {%8,%9}, {%0,%1,%2,%3};\n"
        : "+f"(d0), "+f"(d1), "+f"(d2), "+f"(d3)
        : "r"(a0), "r"(a1), "r"(a2), "r"(a3), "r"(b0), "r"(b1));
}

// split-bf16: d += Ahi*Bhi + Ahi*Blo + Alo*Bhi
__device__ __forceinline__ void mma3(float* d, uint2 a0, uint2 a1, uint2 a2, uint2 a3,
                                     uint2 b0, uint2 b1) {
    mma16816(d[0], d[1], d[2], d[3], a0.x, a1.x, a2.x, a3.x, b0.x, b1.x);
    mma16816(d[0], d[1], d[2], d[3], a0.x, a1.x, a2.x, a3.x, b0.y, b1.y);
    mma16816(d[0], d[1], d[2], d[3], a0.y, a1.y, a2.y, a3.y, b0.x, b1.x);
}

// CG-style grid barrier: release-atomic arrive, acquire-poll on generation.
__device__ __forceinline__ void gbar() {
    __syncthreads();
    if (threadIdx.x == 0) {
        unsigned g;
        asm volatile("ld.relaxed.gpu.u32 %0, [%1];" : "=r"(g) : "l"(&d_gen));
        unsigned prev;
        asm volatile("atom.release.gpu.add.u32 %0, [%1], %2;"
                     : "=r"(prev) : "l"(&d_cnt), "r"(1u) : "memory");
        if (prev == NCTA - 1) {
            asm volatile("st.relaxed.gpu.u32 [%0], %1;" :: "l"(&d_cnt), "r"(0u) : "memory");
            asm volatile("st.release.gpu.u32 [%0], %1;" :: "l"(&d_gen), "r"(g + 1u) : "memory");
        } else {
            unsigned cur;
            do {
                asm volatile("ld.acquire.gpu.u32 %0, [%1];" : "=r"(cur) : "l"(&d_gen) : "memory");
            } while (cur == g);
        }
    }
    __syncthreads();
}

// ---------------- init / packing -----------------------------------------------
__global__ void k_zero_init() {
    int i = threadIdx.x;
    if (i < KP) d_zrow[i] = make_uint2(0u, 0u);
    d_zf[i] = 0.0f; d_zf[i + 512] = 0.0f;
}

__global__ void k_packw(const float* __restrict__ src, uint2* __restrict__ dst, int npairs) {
    int i = blockIdx.x * blockDim.x + threadIdx.x;
    if (i >= npairs) return;
    float2 v = reinterpret_cast<const float2*>(src)[i];
    dst[i] = packpair(v.x, v.y);
}

__global__ void k_gather_pack(const int* __restrict__ ids, const float* __restrict__ embed) {
    int gid = blockIdx.x * blockDim.x + threadIdx.x;
    const int total = NROWS * KPE;
    if (gid >= total) return;
    int r   = gid / KPE;
    int c   = gid % KPE;
    int s   = r / (TSTEP*BB);
    int rem = r % (TSTEP*BB);
    int t   = rem / BB;
    int b   = rem % BB;
    int tok = ids[(s*BB + b)*TT + t];
    float2 v = reinterpret_cast<const float2*>(embed + (size_t)tok*EE)[c];
    d_xp[(size_t)r*KPE + c] = packpair(v.x, v.y);
}

// ---------------- big GEMM: C[M=3840, N=3072] = A @ Bw^T + bias -----------------
__global__ __launch_bounds__(256)
void k_mma_big(const uint2* __restrict__ A, const uint2* __restrict__ Bw,
               const float* __restrict__ bias, float* __restrict__ C, int Kp)
{
    int wid = threadIdx.x >> 5, lane = threadIdx.x & 31;
    int g = lane >> 2, tg = lane & 3;
    int wm = wid >> 2, wn = wid & 3;
    int m0 = blockIdx.x * 128 + wm * 64;
    int n0 = blockIdx.y * 128 + wn * 32;

    float acc[4][4][4];
#pragma unroll
    for (int mi = 0; mi < 4; mi++)
#pragma unroll
        for (int q = 0; q < 4; q++)
#pragma unroll
            for (int i = 0; i < 4; i++) acc[mi][q][i] = 0.0f;

#pragma unroll 2
    for (int kc = 0; kc < Kp; kc += 8) {
        uint2 a[4][4];
#pragma unroll
        for (int mi = 0; mi < 4; mi++) {
            const uint2* Ar0 = A + (size_t)(m0 + mi*16 + g    ) * Kp + kc + tg;
            const uint2* Ar1 = A + (size_t)(m0 + mi*16 + g + 8) * Kp + kc + tg;
            a[mi][0] = Ar0[0];
            a[mi][2] = Ar0[4];
            a[mi][1] = Ar1[0];
            a[mi][3] = Ar1[4];
        }
#pragma unroll
        for (int q = 0; q < 4; q++) {
            const uint2* Br = Bw + (size_t)(n0 + 8*q + g) * Kp + kc + tg;
            uint2 b0 = Br[0];
            uint2 b1 = Br[4];
#pragma unroll
            for (int mi = 0; mi < 4; mi++)
                mma3(acc[mi][q], a[mi][0], a[mi][1], a[mi][2], a[mi][3], b0, b1);
        }
    }

#pragma unroll
    for (int mi = 0; mi < 4; mi++) {
        int mA = m0 + mi*16 + g;
        int mB = mA + 8;
#pragma unroll
        for (int q = 0; q < 4; q++) {
            int col = n0 + 8*q + 2*tg;
            float b0v = bias[col], b1v = bias[col+1];
            *(float2*)(C + (size_t)mA*GG + col) = make_float2(acc[mi][q][0] + b0v, acc[mi][q][1] + b1v);
            *(float2*)(C + (size_t)mB*GG + col) = make_float2(acc[mi][q][2] + b0v, acc[mi][q][3] + b1v);
        }
    }
}

// ---------------- persistent single-layer recurrence (W cached in SMEM) ---------
// Each CTA owns 8 h-outputs (24 gate rows). The 24x512-uint2 weight slice (98KB)
// is copied to shared memory ONCE; the 120-step loop reads W only from smem.
// One grid barrier per step.
__global__ __launch_bounds__(256, 1)
void k_recur(const uint2* __restrict__ W,      // [GG][KP] packed (W_hh)
             const float* __restrict__ gi,     // [NROWS][GG] input gates (+b_ih)
             const float* __restrict__ bias,   // [GG] b_hh
             float* __restrict__ hs,           // [NROWS][HH]
             uint2* __restrict__ hsp,          // [NROWS][KP]
             const int* __restrict__ lens)
{
    extern __shared__ uint2 Ws[];              // [24][WSTRIDE] weight slice
    __shared__ float Sp[8][24][33];            // per-warp gate partials
    __shared__ float hbuf[32*9];               // h outputs (padded)
    __shared__ const uint2* xptr[BB];          // per-batch packed hprev row
    __shared__ const float* hpv [BB];          // per-batch fp32 hprev row

    int tid  = threadIdx.x;
    int w    = tid >> 5, lane = tid & 31;
    int g    = lane >> 2, tg = lane & 3;
    int j0   = blockIdx.x * JT;
    int kb   = w * 64;                         // per-warp K chunk (uint2)

    // ---- one-time: copy this CTA's 24 gate rows into smem ----
    for (int idx = tid; idx < 24*KP; idx += 256) {
        int r24 = idx >> 9;                    // 0..23
        int c   = idx & 511;
        int grow = (r24 < 8) ? (j0 + r24)
                 : (r24 < 16) ? (HH + j0 + (r24 - 8))
                 : (2*HH + j0 + (r24 - 16));
        Ws[r24*WSTRIDE + c] = W[(size_t)grow*KP + c];
    }
    __syncthreads();

    const uint2* WsR = Ws + (size_t)(g      ) * WSTRIDE;
    const uint2* WsZ = Ws + (size_t)(8 + g  ) * WSTRIDE;
    const uint2* WsN = Ws + (size_t)(16 + g ) * WSTRIDE;

    // pointwise mapping: thread -> (j = tid>>5, b = lane)
    int pj = tid >> 5, pb = lane;
    float bR = bias[j0 + pj];
    float bZ = bias[HH + j0 + pj];
    float bN = bias[2*HH + j0 + pj];

    for (int s = 0; s < SS; s++) {
        for (int t = 0; t < TSTEP; t++) {
            int step = s*TSTEP + t;

            // per-batch hprev row pointers (handles sentence carry + zero init)
            if (tid < BB) {
                int b = tid;
                const uint2* xp; const float* hp;
                if (t == 0) {
                    if (s == 0) { xp = d_zrow; hp = d_zf; }
                    else {
                        int idx = lens[(s-1)*BB + b] - 2;
                        idx = idx < 0 ? 0 : (idx > TSTEP-1 ? TSTEP-1 : idx);
                        size_t r = (size_t)((s-1)*TSTEP + idx)*BB + b;
                        xp = hsp + r*KP; hp = hs + r*HH;
                    }
                } else {
                    size_t r = (size_t)(step-1)*BB + b;
                    xp = hsp + r*KP; hp = hs + r*HH;
                }
                xptr[b] = xp; hpv[b] = hp;
            }
            __syncthreads();

            // ---- fused gate GEMM: W from smem, x from L2 ----
            const uint2* x0 = xptr[g];
            const uint2* x1 = xptr[8+g];
            const uint2* x2 = xptr[16+g];
            const uint2* x3 = xptr[24+g];

            float acc0[4][4], acc1[4][4];
#pragma unroll
            for (int q = 0; q < 4; q++)
#pragma unroll
                for (int i = 0; i < 4; i++) { acc0[q][i] = 0.0f; acc1[q][i] = 0.0f; }

#pragma unroll
            for (int kk = 0; kk < 8; kk++) {
                int kc = kb + kk*8;
                // hoist all x-fragments for this k16 step (MLP)
                uint2 xb[4][2];
                xb[0][0] = x0[kc+tg]; xb[0][1] = x0[kc+tg+4];
                xb[1][0] = x1[kc+tg]; xb[1][1] = x1[kc+tg+4];
                xb[2][0] = x2[kc+tg]; xb[2][1] = x2[kc+tg+4];
                xb[3][0] = x3[kc+tg]; xb[3][1] = x3[kc+tg+4];

                uint2 ar0 = WsR[kc+tg], ar4 = WsR[kc+tg+4];
                uint2 az0 = WsZ[kc+tg], az4 = WsZ[kc+tg+4];
                uint2 an0 = WsN[kc+tg], an4 = WsN[kc+tg+4];
#pragma unroll
                for (int q = 0; q < 4; q++) {
                    mma3(acc0[q], ar0, az0, ar4, az4, xb[q][0], xb[q][1]);
                    mma3(acc1[q], an0, ar0, an4, ar4, xb[q][0], xb[q][1]);
                }
            }

            // store per-warp partials
#pragma unroll
            for (int q = 0; q < 4; q++) {
                int col = q*8 + 2*tg;
                Sp[w][g     ][col]   = acc0[q][0];
                Sp[w][g     ][col+1] = acc0[q][1];
                Sp[w][8 + g ][col]   = acc0[q][2];
                Sp[w][8 + g ][col+1] = acc0[q][3];
                Sp[w][16 + g][col]   = acc1[q][0];
                Sp[w][16 + g][col+1] = acc1[q][1];
            }
            __syncthreads();

            // ---- reduce 8 warps + GRU pointwise (one thread per (j,b)) ----
            {
                float sr = 0.f, sz = 0.f, sn = 0.f;
#pragma unroll
                for (int ww = 0; ww < 8; ww++) {
                    sr += Sp[ww][pj     ][pb];
                    sz += Sp[ww][8 + pj ][pb];
                    sn += Sp[ww][16 + pj][pb];
                }
                const float* gir = gi + ((size_t)step*BB + pb) * GG;
                float ir  = gir[j0 + pj];
                float iz  = gir[HH + j0 + pj];
                float inn = gir[2*HH + j0 + pj];
                float hprev = hpv[pb][j0 + pj];

                float rr = 1.0f / (1.0f + expf(-(ir + sr + bR)));
                float zz = 1.0f / (1.0f + expf(-(iz + sz + bZ)));
                float nn = tanhf(inn + rr * (sn + bN));
                hbuf[pb*9 + pj] = (1.0f - zz)*nn + zz*hprev;
            }
            __syncthreads();

            // ---- write h (fp32 + packed) ----
            {
                int b = tid >> 3, j = tid & 7;
                size_t row = (size_t)step*BB + b;
                hs[row*HH + j0 + j] = hbuf[b*9 + j];
            }
            if (tid < 128) {
                int b = tid >> 2, jp = tid & 3;
                size_t row = (size_t)step*BB + b;
                hsp[row*KP + (j0 >> 1) + jp] = packpair(hbuf[b*9 + 2*jp], hbuf[b*9 + 2*jp + 1]);
            }

            gbar();   // ONE global sync per step
        }
    }
}

// ---------------- logits GEMM via split-bf16 mma --------------------------------
__global__ __launch_bounds__(256)
void k_mma_logits(float* __restrict__ out)
{
    int wid = threadIdx.x >> 5, lane = threadIdx.x & 31;
    int g = lane >> 2, tg = lane & 3;
    int wm = wid >> 2, wn = wid & 3;
    int m0 = blockIdx.x * 128 + wm * 64;
    int n0 = blockIdx.y * 128 + wn * 32;

    float acc[4][4][4];
#pragma unroll
    for (int mi = 0; mi < 4; mi++)
#pragma unroll
        for (int q = 0; q < 4; q++)
#pragma unroll
            for (int i = 0; i < 4; i++) acc[mi][q][i] = 0.0f;

#pragma unroll 2
    for (int kc = 0; kc < KP; kc += 8) {
        uint2 a[4][4];
#pragma unroll
        for (int mi = 0; mi < 4; mi++) {
            const uint2* Ar0 = d_hs1p + (size_t)(m0 + mi*16 + g    ) * KP + kc + tg;
            const uint2* Ar1 = d_hs1p + (size_t)(m0 + mi*16 + g + 8) * KP + kc + tg;
            a[mi][0] = Ar0[0];
            a[mi][2] = Ar0[4];
            a[mi][1] = Ar1[0];
            a[mi][3] = Ar1[4];
        }
#pragma unroll
        for (int q = 0; q < 4; q++) {
            const uint2* Br = d_WpO + (size_t)(n0 + 8*q + g) * KP + kc + tg;
            uint2 b0 = Br[0];
            uint2 b1 = Br[4];
#pragma unroll
            for (int mi = 0; mi < 4; mi++)
                mma3(acc[mi][q], a[mi][0], a[mi][1], a[mi][2], a[mi][3], b0, b1);
        }
    }

    // epilogue with (s,t,b)->(s,b,t) remap
#pragma unroll
    for (int mi = 0; mi < 4; mi++) {
        int mA = m0 + mi*16 + g;
        int mB = mA + 8;
        int sA = mA / (TSTEP*BB); int rA = mA % (TSTEP*BB);
        int sB = mB / (TSTEP*BB); int rB = mB % (TSTEP*BB);
        size_t rowA = ((size_t)(sA*BB + (rA % BB))*TSTEP + (rA / BB)) * VV;
        size_t rowB = ((size_t)(sB*BB + (rB % BB))*TSTEP + (rB / BB)) * VV;
#pragma unroll
        for (int q = 0; q < 4; q++) {
            int col = n0 + 8*q + 2*tg;
            *(float2*)(out + rowA + col) = make_float2(acc[mi][q][0], acc[mi][q][1]);
            *(float2*)(out + rowB + col) = make_float2(acc[mi][q][2], acc[mi][q][3]);
        }
    }
}

// ---------------- launcher ------------------------------------------------------
extern "C" void kernel_launch(void* const* d_in, const int* in_sizes, int n_in,
                              void* d_out, int out_size)
{
    (void)in_sizes; (void)n_in; (void)out_size;
    const int*   ids    = (const int*)  d_in[0];
    const int*   lens   = (const int*)  d_in[1];
    const float* embed  = (const float*)d_in[2];
    const float* W_ih0  = (const float*)d_in[3];
    const float* W_hh0  = (const float*)d_in[4];
    const float* b_ih0  = (const float*)d_in[5];
    const float* b_hh0  = (const float*)d_in[6];
    const float* W_ih1  = (const float*)d_in[7];
    const float* W_hh1  = (const float*)d_in[8];
    const float* b_ih1  = (const float*)d_in[9];
    const float* b_hh1  = (const float*)d_in[10];
    const float* W_out  = (const float*)d_in[11];
    float*       out    = (float*)d_out;

    uint2* wpi0; cudaGetSymbolAddress((void**)&wpi0, d_WpI0);
    uint2* wp0;  cudaGetSymbolAddress((void**)&wp0,  d_Wp0);
    uint2* wp1i; cudaGetSymbolAddress((void**)&wp1i, d_Wp1i);
    uint2* wp1h; cudaGetSymbolAddress((void**)&wp1h, d_Wp1h);
    uint2* wpo;  cudaGetSymbolAddress((void**)&wpo,  d_WpO);
    uint2* xp;   cudaGetSymbolAddress((void**)&xp,   d_xp);
    uint2* h0p;  cudaGetSymbolAddress((void**)&h0p,  d_hs0p);
    uint2* h1p;  cudaGetSymbolAddress((void**)&h1p,  d_hs1p);
    float* gi;   cudaGetSymbolAddress((void**)&gi,   d_gi);
    float* hs0;  cudaGetSymbolAddress((void**)&hs0,  d_hs0);
    float* hs1;  cudaGetSymbolAddress((void**)&hs1,  d_hs1);

    // opt-in to >48KB dynamic smem for the recurrence kernel (idempotent; the
    // first, non-captured correctness call sets it persistently)
    const int WS_BYTES = 24 * WSTRIDE * sizeof(uint2);   // 98,496 B
    cudaFuncSetAttribute(k_recur, cudaFuncAttributeMaxDynamicSharedMemorySize, WS_BYTES);

    // zero rows + gather/pack inputs
    k_zero_init<<<1, 512>>>();
    k_gather_pack<<<(NROWS*KPE + 255)/256, 256>>>(ids, embed);
    k_packw<<<(GG*KPE + 255)/256, 256>>>(W_ih0, wpi0, GG*KPE);
    k_packw<<<(GG*KP  + 255)/256, 256>>>(W_hh0, wp0,  GG*KP);
    k_packw<<<(GG*KP  + 255)/256, 256>>>(W_ih1, wp1i, GG*KP);
    k_packw<<<(GG*KP  + 255)/256, 256>>>(W_hh1, wp1h, GG*KP);
    k_packw<<<(VV*KP  + 255)/256, 256>>>(W_out, wpo,  VV*KP);

    // gi(layer0) = x @ W_ih0^T + b_ih0
    k_mma_big<<<dim3(NROWS/128, GG/128), 256>>>(xp, wpi0, b_ih0, gi, KPE);

    // layer-0 recurrence (persistent, W in smem, 1 barrier/step)
    k_recur<<<NCTA, 256, WS_BYTES>>>(wp0, gi, b_hh0, hs0, h0p, lens);

    // gi(layer1) = h0_all @ W_ih1^T + b_ih1  (off critical path, one big GEMM)
    k_mma_big<<<dim3(NROWS/128, GG/128), 256>>>(h0p, wp1i, b_ih1, gi, KP);

    // layer-1 recurrence
    k_recur<<<NCTA, 256, WS_BYTES>>>(wp1h, gi, b_hh1, hs1, h1p, lens);

    // logits = hs1 @ W_out^T, remapped to (s, b, t, v)
    k_mma_logits<<<dim3(NROWS/128, VV/128), 256>>>(out);
}

// round 14
// speedup vs baseline: 2.0133x; 1.1378x over previous
#include <cuda_runtime.h>
#include <cuda_bf16.h>
#include <stdint.h>
#include <math.h>

// Problem constants
#define SS     5
#define BB     32
#define TT     25
#define TSTEP  24          // T-1 recurrence steps
#define VV     32000
#define EE     512
#define HH     1024
#define GG     3072        // 3*H
#define NROWS  (SS*TSTEP*BB)   // 3840
#define KP     (HH/2)      // 512 packed uint2 per row (hi-pair, lo-pair)
#define KPE    (EE/2)      // 256 packed uint2 per embedding row
#define NCTA   128         // persistent recurrence grid (1 CTA per 8 h-outputs)
#define JT     8           // h outputs per CTA
#define WSTRIDE 520        // smem row stride (uint2): 4160B = 16B-aligned, LDS.128 conflict-free

// Pair-position permutation within each 8-pair group: slot -> (slot&3)*2 + (slot>>2).
// Puts pairs (tg, tg+4) adjacent so consumers use one 16B load per fragment pair.
__host__ __device__ __forceinline__ int permpos(int p) {
    int grp = p >> 3, slot = p & 7;
    return grp*8 + ((slot & 3)*2 + (slot >> 2));
}

// ---------------- scratch (static device globals; no allocation) ----------------
__device__ float d_gi  [(size_t)NROWS * GG];         // gi buffer (layer0, then layer1)
__device__ float d_hs0 [(size_t)NROWS * HH];         // layer0 hidden (fp32)
__device__ float d_hs1 [(size_t)NROWS * HH];         // layer1 hidden (fp32)

// packed split-bf16 (PERMUTED layout): uint2 {x = hi|hi<<16, y = lo|lo<<16}
__device__ uint2 d_xp  [(size_t)NROWS*KPE];          // embeddings packed
__device__ uint2 d_WpI0[(size_t)GG*KPE];             // W_ih0 packed
__device__ uint2 d_Wp0 [(size_t)GG*KP];              // W_hh0 packed
__device__ uint2 d_Wp1i[(size_t)GG*KP];              // W_ih1 packed
__device__ uint2 d_Wp1h[(size_t)GG*KP];              // W_hh1 packed
__device__ uint2 d_WpO [(size_t)VV*KP];              // W_out packed (131MB)
__device__ uint2 d_hs0p[(size_t)NROWS*KP];           // layer0 hidden packed
__device__ uint2 d_hs1p[(size_t)NROWS*KP];           // layer1 hidden packed
__device__ uint2 d_zrow[KP];                         // zero packed row
__device__ float d_zf  [HH];                         // zero fp32 row

// grid barrier state (separate lines)
__device__ unsigned d_cnt = 0;
__device__ unsigned d_padA[31];
__device__ unsigned d_gen = 0;

// ---------------- helpers -------------------------------------------------------
__device__ __forceinline__ uint2 packpair(float x, float y) {
    __nv_bfloat16 hx = __float2bfloat16_rn(x);
    __nv_bfloat16 hy = __float2bfloat16_rn(y);
    float rx = x - __bfloat162float(hx);
    float ry = y - __bfloat162float(hy);
    __nv_bfloat16 lx = __float2bfloat16_rn(rx);
    __nv_bfloat16 ly = __float2bfloat16_rn(ry);
    uint2 o;
    o.x = (unsigned int)__bfloat16_as_ushort(hx) | ((unsigned int)__bfloat16_as_ushort(hy) << 16);
    o.y = (unsigned int)__bfloat16_as_ushort(lx) | ((unsigned int)__bfloat16_as_ushort(ly) << 16);
    return o;
}

__device__ __forceinline__ void mma16816(float& d0, float& d1, float& d2, float& d3,
                                         unsigned int a0, unsigned int a1,
                                         unsigned int a2, unsigned int a3,
                                         unsigned int b0, unsigned int b1) {
    asm volatile(
        "mma.sync.aligned.m16n8k16.row.col.f32.bf16.bf16.f32 "
        "{%0,%1,%2,%3}, {%4,%5,%6,%7}, {%8,%9}, {%0,%1,%2,%3};\n"
        : "+f"(d0), "+f"(d1), "+f"(d2), "+f"(d3)
        : "r"(a0), "r"(a1), "r"(a2), "r"(a3), "r"(b0), "r"(b1));
}

// split-bf16 with uint4 fragments: va = {pair tg: hi,lo, pair tg+4: hi,lo} per row
// d += Ahi*Bhi + Ahi*Blo + Alo*Bhi
__device__ __forceinline__ void mma3v(float* d, uint4 v0, uint4 v1, uint4 vb) {
    mma16816(d[0], d[1], d[2], d[3], v0.x, v1.x, v0.z, v1.z, vb.x, vb.z);
    mma16816(d[0], d[1], d[2], d[3], v0.x, v1.x, v0.z, v1.z, vb.y, vb.w);
    mma16816(d[0], d[1], d[2], d[3], v0.y, v1.y, v0.w, v1.w, vb.x, vb.z);
}

// CG-style grid barrier: release-atomic arrive, acquire-poll on generation.
__device__ __forceinline__ void gbar() {
    __syncthreads();
    if (threadIdx.x == 0) {
        unsigned g;
        asm volatile("ld.relaxed.gpu.u32 %0, [%1];" : "=r"(g) : "l"(&d_gen));
        unsigned prev;
        asm volatile("atom.release.gpu.add.u32 %0, [%1], %2;"
                     : "=r"(prev) : "l"(&d_cnt), "r"(1u) : "memory");
        if (prev == NCTA - 1) {
            asm volatile("st.relaxed.gpu.u32 [%0], %1;" :: "l"(&d_cnt), "r"(0u) : "memory");
            asm volatile("st.release.gpu.u32 [%0], %1;" :: "l"(&d_gen), "r"(g + 1u) : "memory");
        } else {
            unsigned cur;
            do {
                asm volatile("ld.acquire.gpu.u32 %0, [%1];" : "=r"(cur) : "l"(&d_gen) : "memory");
            } while (cur == g);
        }
    }
    __syncthreads();
}

// ---------------- init / packing -----------------------------------------------
__global__ void k_zero_init() {
    int i = threadIdx.x;
    if (i < KP) d_zrow[i] = make_uint2(0u, 0u);
    d_zf[i] = 0.0f; d_zf[i + 512] = 0.0f;
}

// pack + permute (rows are multiples of 8 pairs, so flat grouping == per-row grouping)
__global__ void k_packw(const float* __restrict__ src, uint2* __restrict__ dst, int npairs) {
    int i = blockIdx.x * blockDim.x + threadIdx.x;
    if (i >= npairs) return;
    float2 v = reinterpret_cast<const float2*>(src)[i];
    dst[permpos(i)] = packpair(v.x, v.y);
}

__global__ void k_gather_pack(const int* __restrict__ ids, const float* __restrict__ embed) {
    int gid = blockIdx.x * blockDim.x + threadIdx.x;
    const int total = NROWS * KPE;
    if (gid >= total) return;
    int r   = gid / KPE;
    int c   = gid % KPE;
    int s   = r / (TSTEP*BB);
    int rem = r % (TSTEP*BB);
    int t   = rem / BB;
    int b   = rem % BB;
    int tok = ids[(s*BB + b)*TT + t];
    float2 v = reinterpret_cast<const float2*>(embed + (size_t)tok*EE)[c];
    d_xp[(size_t)r*KPE + permpos(c)] = packpair(v.x, v.y);
}

// ---------------- big GEMM: C[M=3840, N=3072] = A @ Bw^T + bias -----------------
// CTA 128x128, 8 warps (2x4), warp 64x32. One LDG.128 per fragment pair.
__global__ __launch_bounds__(256)
void k_mma_big(const uint2* __restrict__ A, const uint2* __restrict__ Bw,
               const float* __restrict__ bias, float* __restrict__ C, int Kp)
{
    int wid = threadIdx.x >> 5, lane = threadIdx.x & 31;
    int g = lane >> 2, tg = lane & 3;
    int wm = wid >> 2, wn = wid & 3;
    int m0 = blockIdx.x * 128 + wm * 64;
    int n0 = blockIdx.y * 128 + wn * 32;

    float acc[4][4][4];
#pragma unroll
    for (int mi = 0; mi < 4; mi++)
#pragma unroll
        for (int q = 0; q < 4; q++)
#pragma unroll
            for (int i = 0; i < 4; i++) acc[mi][q][i] = 0.0f;

#pragma unroll 2
    for (int kc = 0; kc < Kp; kc += 8) {
        uint4 a0[4], a1[4];
#pragma unroll
        for (int mi = 0; mi < 4; mi++) {
            a0[mi] = *(const uint4*)(A + (size_t)(m0 + mi*16 + g    ) * Kp + kc + 2*tg);
            a1[mi] = *(const uint4*)(A + (size_t)(m0 + mi*16 + g + 8) * Kp + kc + 2*tg);
        }
#pragma unroll
        for (int q = 0; q < 4; q++) {
            uint4 vb = *(const uint4*)(Bw + (size_t)(n0 + 8*q + g) * Kp + kc + 2*tg);
#pragma unroll
            for (int mi = 0; mi < 4; mi++)
                mma3v(acc[mi][q], a0[mi], a1[mi], vb);
        }
    }

#pragma unroll
    for (int mi = 0; mi < 4; mi++) {
        int mA = m0 + mi*16 + g;
        int mB = mA + 8;
#pragma unroll
        for (int q = 0; q < 4; q++) {
            int col = n0 + 8*q + 2*tg;
            float b0v = bias[col], b1v = bias[col+1];
            *(float2*)(C + (size_t)mA*GG + col) = make_float2(acc[mi][q][0] + b0v, acc[mi][q][1] + b1v);
            *(float2*)(C + (size_t)mB*GG + col) = make_float2(acc[mi][q][2] + b0v, acc[mi][q][3] + b1v);
        }
    }
}

// ---------------- persistent single-layer recurrence (W cached in SMEM) ---------
__global__ __launch_bounds__(256, 1)
void k_recur(const uint2* __restrict__ W,      // [GG][KP] packed+permuted (W_hh)
             const float* __restrict__ gi,     // [NROWS][GG] input gates (+b_ih)
             const float* __restrict__ bias,   // [GG] b_hh
             float* __restrict__ hs,           // [NROWS][HH]
             uint2* __restrict__ hsp,          // [NROWS][KP] packed+permuted
             const int* __restrict__ lens)
{
    extern __shared__ uint2 Ws[];              // [24][WSTRIDE] weight slice
    __shared__ float Sp[8][24][33];            // per-warp gate partials
    __shared__ float hbuf[32*9];               // h outputs (padded)
    __shared__ const uint2* xptr[BB];          // per-batch packed hprev row
    __shared__ const float* hpv [BB];          // per-batch fp32 hprev row

    int tid  = threadIdx.x;
    int w    = tid >> 5, lane = tid & 31;
    int g    = lane >> 2, tg = lane & 3;
    int j0   = blockIdx.x * JT;
    int kb   = w * 64;                         // per-warp K chunk (uint2)

    // ---- one-time: copy this CTA's 24 gate rows into smem (layout preserved) ----
    for (int idx = tid; idx < 24*KP; idx += 256) {
        int r24 = idx >> 9;                    // 0..23
        int c   = idx & 511;
        int grow = (r24 < 8) ? (j0 + r24)
                 : (r24 < 16) ? (HH + j0 + (r24 - 8))
                 : (2*HH + j0 + (r24 - 16));
        Ws[r24*WSTRIDE + c] = W[(size_t)grow*KP + c];
    }
    __syncthreads();

    const uint2* WsR = Ws + (size_t)(g      ) * WSTRIDE;
    const uint2* WsZ = Ws + (size_t)(8 + g  ) * WSTRIDE;
    const uint2* WsN = Ws + (size_t)(16 + g ) * WSTRIDE;

    // pointwise mapping: thread -> (j = tid>>5, b = lane)
    int pj = tid >> 5, pb = lane;
    float bR = bias[j0 + pj];
    float bZ = bias[HH + j0 + pj];
    float bN = bias[2*HH + j0 + pj];

    for (int s = 0; s < SS; s++) {
        for (int t = 0; t < TSTEP; t++) {
            int step = s*TSTEP + t;

            // per-batch hprev row pointers (handles sentence carry + zero init)
            if (tid < BB) {
                int b = tid;
                const uint2* xp; const float* hp;
                if (t == 0) {
                    if (s == 0) { xp = d_zrow; hp = d_zf; }
                    else {
                        int idx = lens[(s-1)*BB + b] - 2;
                        idx = idx < 0 ? 0 : (idx > TSTEP-1 ? TSTEP-1 : idx);
                        size_t r = (size_t)((s-1)*TSTEP + idx)*BB + b;
                        xp = hsp + r*KP; hp = hs + r*HH;
                    }
                } else {
                    size_t r = (size_t)(step-1)*BB + b;
                    xp = hsp + r*KP; hp = hs + r*HH;
                }
                xptr[b] = xp; hpv[b] = hp;
            }
            __syncthreads();

            // ---- fused gate GEMM: W from smem (LDS.128), x from L2 (LDG.128) ----
            const uint2* x0 = xptr[g];
            const uint2* x1 = xptr[8+g];
            const uint2* x2 = xptr[16+g];
            const uint2* x3 = xptr[24+g];

            float acc0[4][4], acc1[4][4];
#pragma unroll
            for (int q = 0; q < 4; q++)
#pragma unroll
                for (int i = 0; i < 4; i++) { acc0[q][i] = 0.0f; acc1[q][i] = 0.0f; }

#pragma unroll
            for (int kk = 0; kk < 8; kk++) {
                int kc = kb + kk*8 + 2*tg;
                uint4 xb[4];
                xb[0] = *(const uint4*)(x0 + kc);
                xb[1] = *(const uint4*)(x1 + kc);
                xb[2] = *(const uint4*)(x2 + kc);
                xb[3] = *(const uint4*)(x3 + kc);

                uint4 vr = *(const uint4*)(WsR + kc);
                uint4 vz = *(const uint4*)(WsZ + kc);
                uint4 vn = *(const uint4*)(WsN + kc);
#pragma unroll
                for (int q = 0; q < 4; q++) {
                    mma3v(acc0[q], vr, vz, xb[q]);
                    mma3v(acc1[q], vn, vr, xb[q]);
                }
            }

            // store per-warp partials
#pragma unroll
            for (int q = 0; q < 4; q++) {
                int col = q*8 + 2*tg;
                Sp[w][g     ][col]   = acc0[q][0];
                Sp[w][g     ][col+1] = acc0[q][1];
                Sp[w][8 + g ][col]   = acc0[q][2];
                Sp[w][8 + g ][col+1] = acc0[q][3];
                Sp[w][16 + g][col]   = acc1[q][0];
                Sp[w][16 + g][col+1] = acc1[q][1];
            }
            __syncthreads();

            // ---- reduce 8 warps + GRU pointwise (one thread per (j,b)) ----
            {
                float sr = 0.f, sz = 0.f, sn = 0.f;
#pragma unroll
                for (int ww = 0; ww < 8; ww++) {
                    sr += Sp[ww][pj     ][pb];
                    sz += Sp[ww][8 + pj ][pb];
                    sn += Sp[ww][16 + pj][pb];
                }
                const float* gir = gi + ((size_t)step*BB + pb) * GG;
                float ir  = gir[j0 + pj];
                float iz  = gir[HH + j0 + pj];
                float inn = gir[2*HH + j0 + pj];
                float hprev = hpv[pb][j0 + pj];

                float rr = 1.0f / (1.0f + expf(-(ir + sr + bR)));
                float zz = 1.0f / (1.0f + expf(-(iz + sz + bZ)));
                float nn = tanhf(inn + rr * (sn + bN));
                hbuf[pb*9 + pj] = (1.0f - zz)*nn + zz*hprev;
            }
            __syncthreads();

            // ---- write h (fp32 + packed, permuted positions) ----
            {
                int b = tid >> 3, j = tid & 7;
                size_t row = (size_t)step*BB + b;
                hs[row*HH + j0 + j] = hbuf[b*9 + j];
            }
            if (tid < 128) {
                int b = tid >> 2, jp = tid & 3;
                size_t row = (size_t)step*BB + b;
                int p = (j0 >> 1) + jp;
                hsp[row*KP + permpos(p)] = packpair(hbuf[b*9 + 2*jp], hbuf[b*9 + 2*jp + 1]);
            }

            gbar();   // ONE global sync per step
        }
    }
}

// ---------------- logits GEMM via split-bf16 mma --------------------------------
__global__ __launch_bounds__(256)
void k_mma_logits(float* __restrict__ out)
{
    int wid = threadIdx.x >> 5, lane = threadIdx.x & 31;
    int g = lane >> 2, tg = lane & 3;
    int wm = wid >> 2, wn = wid & 3;
    int m0 = blockIdx.x * 128 + wm * 64;
    int n0 = blockIdx.y * 128 + wn * 32;

    float acc[4][4][4];
#pragma unroll
    for (int mi = 0; mi < 4; mi++)
#pragma unroll
        for (int q = 0; q < 4; q++)
#pragma unroll
            for (int i = 0; i < 4; i++) acc[mi][q][i] = 0.0f;

#pragma unroll 2
    for (int kc = 0; kc < KP; kc += 8) {
        uint4 a0[4], a1[4];
#pragma unroll
        for (int mi = 0; mi < 4; mi++) {
            a0[mi] = *(const uint4*)(d_hs1p + (size_t)(m0 + mi*16 + g    ) * KP + kc + 2*tg);
            a1[mi] = *(const uint4*)(d_hs1p + (size_t)(m0 + mi*16 + g + 8) * KP + kc + 2*tg);
        }
#pragma unroll
        for (int q = 0; q < 4; q++) {
            uint4 vb = *(const uint4*)(d_WpO + (size_t)(n0 + 8*q + g) * KP + kc + 2*tg);
#pragma unroll
            for (int mi = 0; mi < 4; mi++)
                mma3v(acc[mi][q], a0[mi], a1[mi], vb);
        }
    }

    // epilogue with (s,t,b)->(s,b,t) remap
#pragma unroll
    for (int mi = 0; mi < 4; mi++) {
        int mA = m0 + mi*16 + g;
        int mB = mA + 8;
        int sA = mA / (TSTEP*BB); int rA = mA % (TSTEP*BB);
        int sB = mB / (TSTEP*BB); int rB = mB % (TSTEP*BB);
        size_t rowA = ((size_t)(sA*BB + (rA % BB))*TSTEP + (rA / BB)) * VV;
        size_t rowB = ((size_t)(sB*BB + (rB % BB))*TSTEP + (rB / BB)) * VV;
#pragma unroll
        for (int q = 0; q < 4; q++) {
            int col = n0 + 8*q + 2*tg;
            *(float2*)(out + rowA + col) = make_float2(acc[mi][q][0], acc[mi][q][1]);
            *(float2*)(out + rowB + col) = make_float2(acc[mi][q][2], acc[mi][q][3]);
        }
    }
}

// ---------------- launcher ------------------------------------------------------
extern "C" void kernel_launch(void* const* d_in, const int* in_sizes, int n_in,
                              void* d_out, int out_size)
{
    (void)in_sizes; (void)n_in; (void)out_size;
    const int*   ids    = (const int*)  d_in[0];
    const int*   lens   = (const int*)  d_in[1];
    const float* embed  = (const float*)d_in[2];
    const float* W_ih0  = (const float*)d_in[3];
    const float* W_hh0  = (const float*)d_in[4];
    const float* b_ih0  = (const float*)d_in[5];
    const float* b_hh0  = (const float*)d_in[6];
    const float* W_ih1  = (const float*)d_in[7];
    const float* W_hh1  = (const float*)d_in[8];
    const float* b_ih1  = (const float*)d_in[9];
    const float* b_hh1  = (const float*)d_in[10];
    const float* W_out  = (const float*)d_in[11];
    float*       out    = (float*)d_out;

    uint2* wpi0; cudaGetSymbolAddress((void**)&wpi0, d_WpI0);
    uint2* wp0;  cudaGetSymbolAddress((void**)&wp0,  d_Wp0);
    uint2* wp1i; cudaGetSymbolAddress((void**)&wp1i, d_Wp1i);
    uint2* wp1h; cudaGetSymbolAddress((void**)&wp1h, d_Wp1h);
    uint2* wpo;  cudaGetSymbolAddress((void**)&wpo,  d_WpO);
    uint2* xp;   cudaGetSymbolAddress((void**)&xp,   d_xp);
    uint2* h0p;  cudaGetSymbolAddress((void**)&h0p,  d_hs0p);
    uint2* h1p;  cudaGetSymbolAddress((void**)&h1p,  d_hs1p);
    float* gi;   cudaGetSymbolAddress((void**)&gi,   d_gi);
    float* hs0;  cudaGetSymbolAddress((void**)&hs0,  d_hs0);
    float* hs1;  cudaGetSymbolAddress((void**)&hs1,  d_hs1);

    const int WS_BYTES = 24 * WSTRIDE * sizeof(uint2);   // 99,840 B
    cudaFuncSetAttribute(k_recur, cudaFuncAttributeMaxDynamicSharedMemorySize, WS_BYTES);

    // zero rows + gather/pack inputs (permuted layout)
    k_zero_init<<<1, 512>>>();
    k_gather_pack<<<(NROWS*KPE + 255)/256, 256>>>(ids, embed);
    k_packw<<<(GG*KPE + 255)/256, 256>>>(W_ih0, wpi0, GG*KPE);
    k_packw<<<(GG*KP  + 255)/256, 256>>>(W_hh0, wp0,  GG*KP);
    k_packw<<<(GG*KP  + 255)/256, 256>>>(W_ih1, wp1i, GG*KP);
    k_packw<<<(GG*KP  + 255)/256, 256>>>(W_hh1, wp1h, GG*KP);
    k_packw<<<(VV*KP  + 255)/256, 256>>>(W_out, wpo,  VV*KP);

    // gi(layer0) = x @ W_ih0^T + b_ih0
    k_mma_big<<<dim3(NROWS/128, GG/128), 256>>>(xp, wpi0, b_ih0, gi, KPE);

    // layer-0 recurrence (persistent, W in smem, 1 barrier/step)
    k_recur<<<NCTA, 256, WS_BYTES>>>(wp0, gi, b_hh0, hs0, h0p, lens);

    // gi(layer1) = h0_all @ W_ih1^T + b_ih1  (off critical path, one big GEMM)
    k_mma_big<<<dim3(NROWS/128, GG/128), 256>>>(h0p, wp1i, b_ih1, gi, KP);

    // layer-1 recurrence
    k_recur<<<NCTA, 256, WS_BYTES>>>(wp1h, gi, b_hh1, hs1, h1p, lens);

    // logits = hs1 @ W_out^T, remapped to (s, b, t, v)
    k_mma_logits<<<dim3(NROWS/128, VV/128), 256>>>(out);
}